// round 3
// baseline (speedup 1.0000x reference)
#include <cuda_runtime.h>

// Problem constants
#define BB 128      // batch
#define TT 1024     // time steps
#define XX 256      // input features
#define HH 512      // hidden
#define G3 1536     // 3*H
#define NCTA 128    // persistent grid for recurrence (<= 148 SMs, all co-resident)
#define ROWS 12     // gate rows per CTA (3 gates x 4 h-cols)
#define JCOLS 4     // h columns per CTA  (128 CTAs * 4 = 512)

// -------- scratch (static device globals; no allocation APIs allowed) --------
__device__ float g_xg[(size_t)TT * G3 * BB];   // [t][gate_row][b], 768 MB
__device__ float g_h[2][HH * BB];              // double-buffered h, [k][b] layout
__device__ unsigned g_bar;                     // grid barrier counter

// ---------------------------------------------------------------------------
// reset: zero h0 and the barrier counter (runs first on every graph replay)
// ---------------------------------------------------------------------------
__global__ void reset_kernel() {
    int i = blockIdx.x * blockDim.x + threadIdx.x;
    if (i == 0) g_bar = 0u;
    if (i < HH * BB) g_h[0][i] = 0.0f;
}

// ---------------------------------------------------------------------------
// Phase 1: xg[t][g][b] = sum_k x[b][t][k] * W_ih[g][k] + b_ih[g]
// grid (12, 1024): blockIdx.x = 128-wide g tile, blockIdx.y = t
// block 256 threads, 128x128 output tile, 8x8 register tiles, K=256
// ---------------------------------------------------------------------------
__global__ void proj_kernel(const float* __restrict__ x,
                            const float* __restrict__ Wih,
                            const float* __restrict__ bih) {
    __shared__ __align__(16) float As[2][8][136];  // [buf][k][g]
    __shared__ __align__(16) float Bs[2][8][136];  // [buf][k][b]

    const int t   = blockIdx.y;
    const int g0  = blockIdx.x * 128;
    const int tid = threadIdx.x;
    const int tx  = tid & 15;   // b tile index (16)
    const int ty  = tid >> 4;   // g tile index (16)

    // loader: each thread fetches one float4 of A and one of B per 8-wide k chunk
    const int lrow = tid >> 1;        // 0..127 : g for A, b for B
    const int lk   = (tid & 1) * 4;   // 0 or 4

    const float* aptr = Wih + (size_t)(g0 + lrow) * XX + lk;
    const float* bptr = x   + ((size_t)lrow * TT + t) * XX + lk;

    float acc[8][8];
#pragma unroll
    for (int i = 0; i < 8; i++)
#pragma unroll
        for (int j = 0; j < 8; j++) acc[i][j] = 0.0f;

    float4 av = *(const float4*)(aptr);
    float4 bv = *(const float4*)(bptr);
    As[0][lk + 0][lrow] = av.x; As[0][lk + 1][lrow] = av.y;
    As[0][lk + 2][lrow] = av.z; As[0][lk + 3][lrow] = av.w;
    Bs[0][lk + 0][lrow] = bv.x; Bs[0][lk + 1][lrow] = bv.y;
    Bs[0][lk + 2][lrow] = bv.z; Bs[0][lk + 3][lrow] = bv.w;
    __syncthreads();

    int buf = 0;
    for (int kc = 0; kc < XX; kc += 8) {
        const bool more = (kc + 8 < XX);
        if (more) {
            av = *(const float4*)(aptr + kc + 8);
            bv = *(const float4*)(bptr + kc + 8);
        }
#pragma unroll
        for (int k = 0; k < 8; k++) {
            float a[8], b[8];
            *(float4*)&a[0] = *(const float4*)&As[buf][k][ty * 8];
            *(float4*)&a[4] = *(const float4*)&As[buf][k][ty * 8 + 4];
            *(float4*)&b[0] = *(const float4*)&Bs[buf][k][tx * 8];
            *(float4*)&b[4] = *(const float4*)&Bs[buf][k][tx * 8 + 4];
#pragma unroll
            for (int i = 0; i < 8; i++)
#pragma unroll
                for (int j = 0; j < 8; j++) acc[i][j] += a[i] * b[j];
        }
        if (more) {
            const int nb = buf ^ 1;
            As[nb][lk + 0][lrow] = av.x; As[nb][lk + 1][lrow] = av.y;
            As[nb][lk + 2][lrow] = av.z; As[nb][lk + 3][lrow] = av.w;
            Bs[nb][lk + 0][lrow] = bv.x; Bs[nb][lk + 1][lrow] = bv.y;
            Bs[nb][lk + 2][lrow] = bv.z; Bs[nb][lk + 3][lrow] = bv.w;
        }
        __syncthreads();
        buf ^= 1;
    }

    // epilogue: add bias, store coalesced to g_xg[t][g][b]
#pragma unroll
    for (int i = 0; i < 8; i++) {
        const int g = g0 + ty * 8 + i;
        const float bias = bih[g];
        float* orow = g_xg + ((size_t)t * G3 + g) * BB + tx * 8;
        float4 v0 = make_float4(acc[i][0] + bias, acc[i][1] + bias,
                                acc[i][2] + bias, acc[i][3] + bias);
        float4 v1 = make_float4(acc[i][4] + bias, acc[i][5] + bias,
                                acc[i][6] + bias, acc[i][7] + bias);
        *(float4*)(orow)     = v0;
        *(float4*)(orow + 4) = v1;
    }
}

// ---------------------------------------------------------------------------
// Phase 2: persistent GRU recurrence.
// 128 CTAs x 128 threads. CTA c owns h columns [4c, 4c+4) => 12 gate rows.
// W_hh slice (12x512, 24KB) stays in SMEM for all 1024 steps.
// h stored transposed [k][b] in global, double buffered; read via __ldcg.
// Each warp covers a 128-wide k slice; partials reduced through SMEM.
// One software grid barrier per step.
// ---------------------------------------------------------------------------
__global__ void gru_kernel(const float* __restrict__ Whh,
                           const float* __restrict__ bhh,
                           float* __restrict__ out) {
    __shared__ __align__(16) float Ws[ROWS][HH];        // 24 KB
    __shared__ __align__(16) float red[4][ROWS][BB];    // 24 KB

    const int c   = blockIdx.x;
    const int j0  = c * JCOLS;
    const int tid = threadIdx.x;

    // load this CTA's 12 W_hh rows: local row rr -> global row (rr/4)*H + j0 + (rr%4)
    for (int idx = tid; idx < ROWS * HH; idx += blockDim.x) {
        const int rr = idx / HH;
        const int k  = idx - rr * HH;
        const int grow = (rr >> 2) * HH + j0 + (rr & 3);
        Ws[rr][k] = Whh[(size_t)grow * HH + k];
    }
    __syncthreads();

    const int warp = tid >> 5;
    const int lane = tid & 31;
    const int bq   = lane * 4;       // 4 consecutive batch elements per lane
    const int k0   = warp * 128;     // k slice per warp
    const unsigned G = gridDim.x;

    for (int t = 0; t < TT; t++) {
        const int p = t & 1;
        const float* __restrict__ hc = g_h[p];

        float acc[ROWS][4];
#pragma unroll
        for (int r = 0; r < ROWS; r++) {
            acc[r][0] = 0.f; acc[r][1] = 0.f; acc[r][2] = 0.f; acc[r][3] = 0.f;
        }

#pragma unroll 4
        for (int k = 0; k < 128; k++) {
            const float4 hv = __ldcg((const float4*)(hc + (size_t)(k0 + k) * BB + bq));
#pragma unroll
            for (int r = 0; r < ROWS; r++) {
                const float w = Ws[r][k0 + k];
                acc[r][0] += w * hv.x;
                acc[r][1] += w * hv.y;
                acc[r][2] += w * hv.z;
                acc[r][3] += w * hv.w;
            }
        }

#pragma unroll
        for (int r = 0; r < ROWS; r++)
            *(float4*)&red[warp][r][bq] =
                make_float4(acc[r][0], acc[r][1], acc[r][2], acc[r][3]);
        __syncthreads();

        // all 128 threads: one batch element each -> reduce + gates + update
        {
            const int b = tid;
            float hg[ROWS];
#pragma unroll
            for (int r = 0; r < ROWS; r++) {
                float s = red[0][r][b] + red[1][r][b] + red[2][r][b] + red[3][r][b];
                hg[r] = s + __ldg(bhh + (r >> 2) * HH + j0 + (r & 3));
            }
            const float* __restrict__ xgt = g_xg + (size_t)t * G3 * BB;
            float* __restrict__ hn = g_h[p ^ 1];
#pragma unroll
            for (int jj = 0; jj < JCOLS; jj++) {
                const int j = j0 + jj;
                const float xr = __ldg(xgt + (size_t)j * BB + b);
                const float xz = __ldg(xgt + (size_t)(HH + j) * BB + b);
                const float xn = __ldg(xgt + (size_t)(2 * HH + j) * BB + b);
                const float rg = 1.0f / (1.0f + __expf(-(xr + hg[jj])));
                const float zg = 1.0f / (1.0f + __expf(-(xz + hg[4 + jj])));
                const float ng = tanhf(xn + rg * hg[8 + jj]);
                const float ho = __ldcg(hc + (size_t)j * BB + b);
                const float hv = (1.0f - zg) * ng + zg * ho;
                hn[(size_t)j * BB + b] = hv;
                if (t == TT - 1) out[(size_t)b * HH + j] = hv;   // [B,H] row-major
            }
        }

        // ---- grid barrier (monotonic counter; reset_kernel zeroes it per launch)
        __threadfence();
        __syncthreads();
        if (tid == 0) {
            atomicAdd(&g_bar, 1u);
            const unsigned target = (unsigned)(t + 1) * G;
            while (*((volatile unsigned*)&g_bar) < target) { }
        }
        __syncthreads();
    }
}

// ---------------------------------------------------------------------------
extern "C" void kernel_launch(void* const* d_in, const int* in_sizes, int n_in,
                              void* d_out, int out_size) {
    const float* x   = (const float*)d_in[0];  // [128,1024,256]
    const float* Wih = (const float*)d_in[1];  // [1536,256]
    const float* Whh = (const float*)d_in[2];  // [1536,512]
    const float* bih = (const float*)d_in[3];  // [1536]
    const float* bhh = (const float*)d_in[4];  // [1536]
    float* out = (float*)d_out;                // [128,512]

    reset_kernel<<<(HH * BB + 255) / 256, 256>>>();
    proj_kernel<<<dim3(12, TT), 256>>>(x, Wih, bih);
    gru_kernel<<<NCTA, 128>>>(Whh, bhh, out);
}

// round 4
// speedup vs baseline: 1.7462x; 1.7462x over previous
#include <cuda_runtime.h>

// Problem constants
#define BB 128      // batch
#define TT 1024     // time steps
#define XX 256      // input features
#define HH 512      // hidden
#define G3 1536     // 3*H
#define NCTA 128    // persistent grid for recurrence (co-resident on 148 SMs)
#define ROWS 12     // gate rows per CTA (3 gates x 4 h-cols)
#define JCOLS 4     // h columns per CTA  (128 CTAs * 4 = 512)

typedef unsigned long long ull;

// -------- scratch (static device globals; no allocation APIs allowed) --------
__device__ float g_xg[(size_t)TT * G3 * BB];   // [t][gate_row][b]
__device__ float g_h[2][HH * BB];              // double-buffered h, [k][b]
__device__ unsigned g_bar;                     // grid barrier counter

// -------- packed f32x2 helpers (Blackwell; PTX-only, ptxas won't auto-fuse) --
__device__ __forceinline__ void ffma2(ull& d, ull a, ull b) {
    asm("fma.rn.f32x2 %0, %1, %2, %0;" : "+l"(d) : "l"(a), "l"(b));
}
__device__ __forceinline__ ull dup2(float v) {
    ull r; asm("mov.b64 %0, {%1, %1};" : "=l"(r) : "f"(v)); return r;
}
__device__ __forceinline__ float2 unpk(ull p) {
    float2 r; asm("mov.b64 {%0, %1}, %2;" : "=f"(r.x), "=f"(r.y) : "l"(p)); return r;
}

// ---------------------------------------------------------------------------
// reset: zero h0 and the barrier counter (runs first on every graph replay)
// ---------------------------------------------------------------------------
__global__ void reset_kernel() {
    int i = blockIdx.x * blockDim.x + threadIdx.x;
    if (i == 0) g_bar = 0u;
    if (i < HH * BB) g_h[0][i] = 0.0f;
}

// ---------------------------------------------------------------------------
// Phase 1: xg[t][g][b] = sum_k x[b][t][k] * W_ih[g][k] + b_ih[g]
// grid (12, 1024), block 256, 128x128 tile, K=256, double-buffered SMEM.
// A stored as duplicated f32x2 pairs (zero-MOV broadcast operand);
// B pairs are natural (contiguous b). Split-tile (tx*4 / 64+tx*4) layout
// keeps LDS.128 conflict-free.
// ---------------------------------------------------------------------------
__global__ __launch_bounds__(256, 2) void proj_kernel(const float* __restrict__ x,
                                                      const float* __restrict__ Wih,
                                                      const float* __restrict__ bih) {
    __shared__ __align__(16) ull   As2[2][8][128];  // duplicated pairs, 16 KB
    __shared__ __align__(16) float Bs[2][8][128];   // 8 KB

    const int t   = blockIdx.y;
    const int g0  = blockIdx.x * 128;
    const int tid = threadIdx.x;
    const int tx  = tid & 15;   // b tile (16)
    const int ty  = tid >> 4;   // g tile (16)

    const int lrow = tid >> 1;        // 0..127
    const int lk   = (tid & 1) * 4;   // 0 or 4

    const float* aptr = Wih + (size_t)(g0 + lrow) * XX + lk;
    const float* bptr = x   + ((size_t)lrow * TT + t) * XX + lk;

    ull acc2[8][4];
#pragma unroll
    for (int i = 0; i < 8; i++)
#pragma unroll
        for (int j = 0; j < 4; j++) acc2[i][j] = 0ull;

    float4 av = *(const float4*)(aptr);
    float4 bv = *(const float4*)(bptr);
    As2[0][lk + 0][lrow] = dup2(av.x); As2[0][lk + 1][lrow] = dup2(av.y);
    As2[0][lk + 2][lrow] = dup2(av.z); As2[0][lk + 3][lrow] = dup2(av.w);
    Bs[0][lk + 0][lrow] = bv.x; Bs[0][lk + 1][lrow] = bv.y;
    Bs[0][lk + 2][lrow] = bv.z; Bs[0][lk + 3][lrow] = bv.w;
    __syncthreads();

    int buf = 0;
    for (int kc = 0; kc < XX; kc += 8) {
        const bool more = (kc + 8 < XX);
        if (more) {
            av = *(const float4*)(aptr + kc + 8);
            bv = *(const float4*)(bptr + kc + 8);
        }
#pragma unroll
        for (int k = 0; k < 8; k++) {
            ulonglong2 a01 = *(const ulonglong2*)&As2[buf][k][ty * 4];
            ulonglong2 a23 = *(const ulonglong2*)&As2[buf][k][ty * 4 + 2];
            ulonglong2 a45 = *(const ulonglong2*)&As2[buf][k][64 + ty * 4];
            ulonglong2 a67 = *(const ulonglong2*)&As2[buf][k][64 + ty * 4 + 2];
            float4 bl = *(const float4*)&Bs[buf][k][tx * 4];
            float4 bh = *(const float4*)&Bs[buf][k][64 + tx * 4];
            const ull* bpl = (const ull*)&bl;   // 2 natural f32x2 pairs
            const ull* bph = (const ull*)&bh;
            ull ad[8] = {a01.x, a01.y, a23.x, a23.y, a45.x, a45.y, a67.x, a67.y};
#pragma unroll
            for (int i = 0; i < 8; i++) {
                ffma2(acc2[i][0], ad[i], bpl[0]);
                ffma2(acc2[i][1], ad[i], bpl[1]);
                ffma2(acc2[i][2], ad[i], bph[0]);
                ffma2(acc2[i][3], ad[i], bph[1]);
            }
        }
        if (more) {
            const int nb = buf ^ 1;
            As2[nb][lk + 0][lrow] = dup2(av.x); As2[nb][lk + 1][lrow] = dup2(av.y);
            As2[nb][lk + 2][lrow] = dup2(av.z); As2[nb][lk + 3][lrow] = dup2(av.w);
            Bs[nb][lk + 0][lrow] = bv.x; Bs[nb][lk + 1][lrow] = bv.y;
            Bs[nb][lk + 2][lrow] = bv.z; Bs[nb][lk + 3][lrow] = bv.w;
        }
        __syncthreads();
        buf ^= 1;
    }

    // epilogue: g rows are split-tile too: i<4 -> g0+ty*4+i, else g0+64+ty*4+(i-4)
#pragma unroll
    for (int i = 0; i < 8; i++) {
        const int g = g0 + ((i < 4) ? (ty * 4 + i) : (64 + ty * 4 + (i - 4)));
        const float bias = bih[g];
        float2 p0 = unpk(acc2[i][0]), p1 = unpk(acc2[i][1]);
        float2 p2 = unpk(acc2[i][2]), p3 = unpk(acc2[i][3]);
        float* orow = g_xg + ((size_t)t * G3 + g) * BB;
        *(float4*)(orow + tx * 4)      = make_float4(p0.x + bias, p0.y + bias,
                                                     p1.x + bias, p1.y + bias);
        *(float4*)(orow + 64 + tx * 4) = make_float4(p2.x + bias, p2.y + bias,
                                                     p3.x + bias, p3.y + bias);
    }
}

// ---------------------------------------------------------------------------
// Phase 2: persistent GRU recurrence, packed f32x2.
// 128 CTAs x 512 threads. CTA c owns h cols [4c,4c+4) => 12 gate rows.
// W_hh slice pre-duplicated (w,w) in SMEM (48KB): one LDS.128 = 2 k of packed
// weights, zero packing MOVs. h in [k][b] layout: one 16B global load = two
// natural f32x2 operands. 16 warps = 2 row-groups x 8 k-slices of 64.
// Per-thread h value lives in a register across all 1024 steps.
// ---------------------------------------------------------------------------
__global__ __launch_bounds__(512, 1) void gru_kernel(const float* __restrict__ Whh,
                                                     const float* __restrict__ bhh,
                                                     float* __restrict__ out) {
    extern __shared__ __align__(16) char smem_raw[];
    ull*   Wsd = (ull*)smem_raw;                          // [ROWS][HH] dup pairs, 48 KB
    float* red = (float*)(smem_raw + ROWS * HH * 8);      // [2][8][6][128], 48 KB

    const int c   = blockIdx.x;
    const int j0  = c * JCOLS;
    const int tid = threadIdx.x;

    // load + duplicate this CTA's 12 W_hh rows
    for (int idx = tid; idx < ROWS * HH; idx += 512) {
        const int rr = idx >> 9;          // /HH
        const int k  = idx & (HH - 1);
        const int grow = (rr >> 2) * HH + j0 + (rr & 3);
        Wsd[rr * HH + k] = dup2(Whh[(size_t)grow * HH + k]);
    }
    __syncthreads();

    const int warp = tid >> 5;
    const int lane = tid & 31;
    const int grp  = warp >> 3;      // row group: rows [grp*6, grp*6+6)
    const int kw   = warp & 7;       // k slice
    const int k0   = kw * 64;
    const int bq   = lane * 4;       // 4 consecutive batch elements

    // epilogue identity: thread owns (b=eb, j=j0+js) forever
    const int eb = tid & 127;
    const int js = tid >> 7;         // 0..3
    float bh[3];
    const float* rp[3];
#pragma unroll
    for (int gate = 0; gate < 3; gate++) {
        bh[gate] = bhh[gate * HH + j0 + js];
        const int rr = gate * 4 + js;
        const int g2 = rr / 6, lr = rr - g2 * 6;
        rp[gate] = &red[((size_t)(g2 * 8) * 6 + lr) * 128 + eb];
    }
    float hval = 0.0f;               // own h element, kept in register

    for (int t = 0; t < TT; t++) {
        const int p = t & 1;
        const float* __restrict__ hc = g_h[p];

        // hoist xg loads: independent of h -> overlap their latency with MMA
        const float* __restrict__ xgt = g_xg + (size_t)t * G3 * BB;
        const float xr = __ldcg(xgt + (size_t)(j0 + js) * BB + eb);
        const float xz = __ldcg(xgt + (size_t)(HH + j0 + js) * BB + eb);
        const float xn = __ldcg(xgt + (size_t)(2 * HH + j0 + js) * BB + eb);

        // ---- packed MMA: 6 rows x 64 k x 4 b per thread
        ull acc[6][2];
#pragma unroll
        for (int r = 0; r < 6; r++) { acc[r][0] = 0ull; acc[r][1] = 0ull; }

        const ull* wbase = Wsd + (size_t)(grp * 6) * HH + k0;
#pragma unroll 4
        for (int k = 0; k < 64; k += 2) {
            const double2 h0d = __ldcg((const double2*)(hc + (size_t)(k0 + k) * BB + bq));
            const double2 h1d = __ldcg((const double2*)(hc + (size_t)(k0 + k + 1) * BB + bq));
            const ull h0a = (ull)__double_as_longlong(h0d.x);
            const ull h0b = (ull)__double_as_longlong(h0d.y);
            const ull h1a = (ull)__double_as_longlong(h1d.x);
            const ull h1b = (ull)__double_as_longlong(h1d.y);
#pragma unroll
            for (int r = 0; r < 6; r++) {
                const ulonglong2 w = *(const ulonglong2*)(wbase + (size_t)r * HH + k);
                ffma2(acc[r][0], w.x, h0a);
                ffma2(acc[r][1], w.x, h0b);
                ffma2(acc[r][0], w.y, h1a);
                ffma2(acc[r][1], w.y, h1b);
            }
        }

        // partials -> SMEM
#pragma unroll
        for (int r = 0; r < 6; r++) {
            float2 q0 = unpk(acc[r][0]), q1 = unpk(acc[r][1]);
            *(float4*)&red[((size_t)(grp * 8 + kw) * 6 + r) * 128 + bq] =
                make_float4(q0.x, q0.y, q1.x, q1.y);
        }
        __syncthreads();

        // ---- epilogue: reduce 8 k-slices, gates, h update (register-resident h)
        {
            float hg[3];
#pragma unroll
            for (int gate = 0; gate < 3; gate++) {
                const float* q = rp[gate];
                float s = q[0];
#pragma unroll
                for (int w = 1; w < 8; w++) s += q[(size_t)w * 6 * 128];
                hg[gate] = s + bh[gate];
            }
            const float rg = 1.0f / (1.0f + __expf(-(xr + hg[0])));
            const float zg = 1.0f / (1.0f + __expf(-(xz + hg[1])));
            const float ng = tanhf(xn + rg * hg[2]);
            hval = (1.0f - zg) * ng + zg * hval;
            g_h[p ^ 1][(size_t)(j0 + js) * BB + eb] = hval;
            if (t == TT - 1) out[(size_t)eb * HH + (j0 + js)] = hval;  // [B,H]
        }

        // ---- grid barrier (monotonic counter, reset per launch)
        __threadfence();
        __syncthreads();
        if (tid == 0) {
            atomicAdd(&g_bar, 1u);
            const unsigned target = (unsigned)(t + 1) * (unsigned)NCTA;
            while (*((volatile unsigned*)&g_bar) < target) { }
        }
        __syncthreads();
    }
}

// ---------------------------------------------------------------------------
extern "C" void kernel_launch(void* const* d_in, const int* in_sizes, int n_in,
                              void* d_out, int out_size) {
    const float* x   = (const float*)d_in[0];  // [128,1024,256]
    const float* Wih = (const float*)d_in[1];  // [1536,256]
    const float* Whh = (const float*)d_in[2];  // [1536,512]
    const float* bih = (const float*)d_in[3];  // [1536]
    const float* bhh = (const float*)d_in[4];  // [1536]
    float* out = (float*)d_out;                // [128,512]

    const int gru_smem = ROWS * HH * 8 + 16 * 6 * 128 * 4;  // 96 KB
    cudaFuncSetAttribute(gru_kernel, cudaFuncAttributeMaxDynamicSharedMemorySize,
                         gru_smem);

    reset_kernel<<<(HH * BB + 255) / 256, 256>>>();
    proj_kernel<<<dim3(12, TT), 256>>>(x, Wih, bih);
    gru_kernel<<<NCTA, 512, gru_smem>>>(Whh, bhh, out);
}